// round 15
// baseline (speedup 1.0000x reference)
#include <cuda_runtime.h>
#include <cuda_fp16.h>
#include <cstdint>

// Problem constants
#define BB   64
#define NN   100
#define DD   2048
#define NRH  16
#define PP   (BB*NN)        // 6400

#define GW_SCALE 1024.0f    // uniform gate scale; cancels exactly in softmax ratio

// ---------------------------------------------------------------------------
// Scratch (__device__ globals; no allocations allowed)
// ---------------------------------------------------------------------------
__device__ __half g_Ah[PP * 2048];               // 26.2 MB  A in fp16 (also V source)
__device__ __half g_Wh[2048 * 2048];             // 8.4 MB   W^T fused [n][k] (Wk|Wq)
__device__ __half g_Kh[PP * 1024];               // 13.1 MB  K fp16
__device__ __half g_Qh[PP * 1024];               // 13.1 MB  Q fp16
__device__ __half g_GW[BB * NRH * NN * NN];      // 20.5 MB  gw*1024 fp16, [b][h][j][i]

__device__ __forceinline__ uint32_t smem_u32(const void* p) {
    uint32_t a;
    asm("{ .reg .u64 t; cvta.to.shared.u64 t, %1; cvt.u32.u64 %0, t; }" : "=r"(a) : "l"(p));
    return a;
}

#define CP_ASYNC16(dst, src) \
    asm volatile("cp.async.cg.shared.global [%0], [%1], 16;" :: "r"(dst), "l"(src) : "memory")
#define CP_COMMIT() asm volatile("cp.async.commit_group;" ::: "memory")
#define CP_WAIT1()  asm volatile("cp.async.wait_group 1;" ::: "memory")
#define CP_WAIT0()  asm volatile("cp.async.wait_group 0;" ::: "memory")

// Non-volatile: barriers fence smem ordering; lets ptxas interleave with mma.
#define LDSM_X4(r0, r1, r2, r3, addr) \
    asm("ldmatrix.sync.aligned.m8n8.x4.shared.b16 {%0,%1,%2,%3}, [%4];" \
        : "=r"(r0), "=r"(r1), "=r"(r2), "=r"(r3) : "r"(addr))

#define LDSM_X4_TRANS(r0, r1, r2, r3, addr) \
    asm("ldmatrix.sync.aligned.m8n8.x4.trans.shared.b16 {%0,%1,%2,%3}, [%4];" \
        : "=r"(r0), "=r"(r1), "=r"(r2), "=r"(r3) : "r"(addr))

__device__ __forceinline__ void mma_fp16(float& c0, float& c1, float& c2, float& c3,
                                         uint32_t a0, uint32_t a1, uint32_t a2, uint32_t a3,
                                         uint32_t b0, uint32_t b1)
{
    asm("mma.sync.aligned.m16n8k16.row.col.f32.f16.f16.f32 "
        "{%0,%1,%2,%3}, {%4,%5,%6,%7}, {%8,%9}, {%0,%1,%2,%3};"
        : "+f"(c0), "+f"(c1), "+f"(c2), "+f"(c3)
        : "r"(a0), "r"(a1), "r"(a2), "r"(a3), "r"(b0), "r"(b1));
}

// ---------------------------------------------------------------------------
// Fused prep: blocks [0, 12800) = A fp32->fp16; [12800, 16896) = W transpose.
// ---------------------------------------------------------------------------
#define PREP_A_BLOCKS 12800
#define PREP_BLOCKS   (PREP_A_BLOCKS + 4096)

__global__ __launch_bounds__(256)
void prep_kernel(const float* __restrict__ A,
                 const float* __restrict__ Wk, const float* __restrict__ Wq)
{
    __shared__ float t[32][33];
    if (blockIdx.x < PREP_A_BLOCKS) {
        int id = blockIdx.x * 256 + threadIdx.x;   // one float4 each
        float4 v = *(const float4*)(A + (size_t)id * 4);
        __half h[4] = {__float2half_rn(v.x), __float2half_rn(v.y),
                       __float2half_rn(v.z), __float2half_rn(v.w)};
        *(uint2*)(g_Ah + (size_t)id * 4) = *(uint2*)h;
    } else {
        int bid = blockIdx.x - PREP_A_BLOCKS;      // 4096 = 64 x 64
        const int k0 = (bid & 63) * 32, n0 = (bid >> 6) * 32;
        const float* src = (n0 < 1024) ? Wk : Wq;
        const int nc0 = (n0 < 1024) ? n0 : n0 - 1024;
        const int tx = threadIdx.x & 31, ty = threadIdx.x >> 5;
        for (int r = ty; r < 32; r += 8)
            t[r][tx] = src[(k0 + r) * 1024 + nc0 + tx];
        __syncthreads();
        for (int r = ty; r < 32; r += 8)
            g_Wh[(size_t)(n0 + r) * 2048 + k0 + tx] = __float2half_rn(t[tx][r]);
    }
}

// ---------------------------------------------------------------------------
// fp16 GEMM: C[6400 x 2048] = Ah @ Wh^T (+bias)  ->  g_Kh | g_Qh (fp16)
// Tiles BM=128 BN=128 BK=64; 3-stage cp.async; 8 warps (2m x 4n), warp 64x32.
// ---------------------------------------------------------------------------
#define ROWH 72
#define ROWB 144
#define TILE_BYTES2 (128 * ROWB)                   // 18432 per operand
#define STAGE_BYTES2 (2 * TILE_BYTES2)             // 36864
#define NSTAGE 3
#define NITER  32                                  // 2048 / 64
#define GEMM_SMEM (NSTAGE * STAGE_BYTES2)          // 110592 B

__global__ __launch_bounds__(256, 2)
void gemm_kernel(const float* __restrict__ bk, const float* __restrict__ bq)
{
    extern __shared__ __align__(16) __half sm[];

    const int tid  = threadIdx.x;
    const int wid  = tid >> 5, lane = tid & 31;
    const int wm   = wid & 1,  wn   = wid >> 1;       // 2 x 4 warp grid
    const int g    = lane >> 2, t4  = lane & 3;
    const int mbase = blockIdx.y * 128;
    const int nbase = blockIdx.x * 128;

    const uint32_t sbase = smem_u32(sm);
    const __half* gA = g_Ah + (size_t)mbase * 2048;
    const __half* gB = g_Wh + (size_t)nbase * 2048;

    auto load_stage = [&](int it, int s) {
        const int k0 = it * 64;
        const uint32_t sA = sbase + s * STAGE_BYTES2;
        const uint32_t sB = sA + TILE_BYTES2;
        #pragma unroll
        for (int l = 0; l < 4; l++) {
            int q = tid + 256 * l;
            int r = q >> 3, c = q & 7;
            CP_ASYNC16(sA + r * ROWB + c * 16,
                       (const char*)(gA + (size_t)r * 2048 + k0 + c * 8));
            CP_ASYNC16(sB + r * ROWB + c * 16,
                       (const char*)(gB + (size_t)r * 2048 + k0 + c * 8));
        }
        CP_COMMIT();
    };

    float c[4][4][4];
    #pragma unroll
    for (int i = 0; i < 4; i++)
        #pragma unroll
        for (int j = 0; j < 4; j++)
            #pragma unroll
            for (int k = 0; k < 4; k++) c[i][j][k] = 0.f;

    load_stage(0, 0);
    load_stage(1, 1);

    const int arow = (lane & 15);
    const int abyt = (lane >> 4) << 4;
    const int brow = (lane & 7) + ((lane >> 4) << 3);
    const int bbyt = ((lane >> 3) & 1) << 4;

    for (int it = 0; it < NITER; ++it) {
        const int s = it % NSTAGE;
        if (it < NITER - 1) { CP_WAIT1(); } else { CP_WAIT0(); }
        __syncthreads();
        if (it + 2 < NITER) load_stage(it + 2, (it + 2) % NSTAGE);

        const uint32_t sA = sbase + s * STAGE_BYTES2;
        const uint32_t sB = sA + TILE_BYTES2;

        #pragma unroll
        for (int ks = 0; ks < 4; ks++) {
            uint32_t af[4][4], bfr[2][4];
            #pragma unroll
            for (int fm = 0; fm < 4; fm++) {
                uint32_t ad = sA + (wm * 64 + fm * 16 + arow) * ROWB + ks * 32 + abyt;
                LDSM_X4(af[fm][0], af[fm][1], af[fm][2], af[fm][3], ad);
            }
            #pragma unroll
            for (int f2 = 0; f2 < 2; f2++) {
                uint32_t bd = sB + (wn * 32 + f2 * 16 + brow) * ROWB + ks * 32 + bbyt;
                LDSM_X4(bfr[f2][0], bfr[f2][1], bfr[f2][2], bfr[f2][3], bd);
            }
            #pragma unroll
            for (int fm = 0; fm < 4; fm++)
                #pragma unroll
                for (int fn = 0; fn < 4; fn++) {
                    uint32_t b0 = bfr[fn >> 1][(fn & 1) * 2 + 0];
                    uint32_t b1 = bfr[fn >> 1][(fn & 1) * 2 + 1];
                    mma_fp16(c[fm][fn][0], c[fm][fn][1], c[fm][fn][2], c[fm][fn][3],
                             af[fm][0], af[fm][1], af[fm][2], af[fm][3], b0, b1);
                }
        }
    }

    const bool side = (nbase >= 1024);
    const float* bsrc = side ? bq : bk;
    __half* outh = side ? g_Qh : g_Kh;
    const int colb = side ? (nbase - 1024) : nbase;

    #pragma unroll
    for (int fm = 0; fm < 4; fm++) {
        int row = mbase + wm * 64 + fm * 16 + g;
        #pragma unroll
        for (int fn = 0; fn < 4; fn++) {
            int col = colb + wn * 32 + fn * 8 + t4 * 2;
            float b0 = bsrc[col], b1 = bsrc[col + 1];
            *(__half2*)(outh + (size_t)row * 1024 + col) =
                __floats2half2_rn(c[fm][fn][0] + b0, c[fm][fn][1] + b1);
            *(__half2*)(outh + (size_t)(row + 8) * 1024 + col) =
                __floats2half2_rn(c[fm][fn][2] + b0, c[fm][fn][3] + b1);
        }
    }
}

// ---------------------------------------------------------------------------
// Gate via fp16 mma, hi/lo split. Rows in (b, j, i)-PERMUTED order so the
// output scatter g_GW[b][h][j][i] keeps contiguous 16B runs per 8 lanes.
// Launched on a LOW-PRIORITY stream CONCURRENT WITH GEMM: gemm's tail wave
// (~88 SMs free for a full wave) has capacity for all 2500 gate CTAs, and
// gate's DRAM traffic hides under tensor-bound gemm (DRAM 2.7%).
// ---------------------------------------------------------------------------
#define GATE_ROWS 256
#define GATE_RH   72
#define ROWB_GATE 144

__global__ __launch_bounds__(256, 2)
void gate_kernel(const float* __restrict__ gf,
                 const float* __restrict__ Wg, const float* __restrict__ bg)
{
    __shared__ __align__(16) __half sGh[GATE_ROWS * GATE_RH];
    __shared__ __align__(16) __half sGl[GATE_ROWS * GATE_RH];

    const int tid = threadIdx.x, lane = tid & 31, wid = tid >> 5;
    const int g = lane >> 2, t4 = lane & 3;
    const int rowbase = blockIdx.x * GATE_ROWS;

    {
        const int r0 = tid >> 4;
        const int c4 = (tid & 15) << 2;
        #pragma unroll
        for (int l = 0; l < 16; l++) {
            int r  = r0 + l * 16;
            int rp = rowbase + r;
            int bb = rp / 10000;
            int remp = rp - bb * 10000;            // = j*100 + i
            int jj = remp / 100;
            int ii = remp - jj * 100;
            float4 x = *(const float4*)(gf + ((size_t)bb * 10000 + ii * 100 + jj) * 64 + c4);
            float xs[4] = {x.x, x.y, x.z, x.w};
            __half hi[4], lo[4];
            #pragma unroll
            for (int e = 0; e < 4; e++) {
                hi[e] = __float2half_rn(xs[e]);
                lo[e] = __float2half_rn(xs[e] - __half2float(hi[e]));
            }
            *(uint2*)(sGh + r * GATE_RH + c4) = *(uint2*)hi;
            *(uint2*)(sGl + r * GATE_RH + c4) = *(uint2*)lo;
        }
    }

    uint32_t bh[4][2][2], bl[4][2][2];
    #pragma unroll
    for (int ks = 0; ks < 4; ks++)
        #pragma unroll
        for (int nt = 0; nt < 2; nt++) {
            int n = nt * 8 + g;
            #pragma unroll
            for (int rg = 0; rg < 2; rg++) {
                int k0 = ks * 16 + t4 * 2 + rg * 8;
                float w0 = Wg[k0 * 16 + n], w1 = Wg[(k0 + 1) * 16 + n];
                __half h0 = __float2half_rn(w0), h1 = __float2half_rn(w1);
                __half l0 = __float2half_rn(w0 - __half2float(h0));
                __half l1 = __float2half_rn(w1 - __half2float(h1));
                __half hh[2] = {h0, h1}, ll[2] = {l0, l1};
                bh[ks][nt][rg] = *(uint32_t*)hh;
                bl[ks][nt][rg] = *(uint32_t*)ll;
            }
        }
    __syncthreads();

    const uint32_t sGhb = smem_u32(sGh), sGlb = smem_u32(sGl);
    const int arow = lane & 15, abyt = (lane >> 4) << 4;
    const int wrow = wid * 32;

    #pragma unroll
    for (int mt = 0; mt < 2; mt++) {
        float c[2][4];
        #pragma unroll
        for (int nt = 0; nt < 2; nt++)
            #pragma unroll
            for (int k = 0; k < 4; k++) c[nt][k] = 0.f;

        #pragma unroll
        for (int ks = 0; ks < 4; ks++) {
            uint32_t ah[4], al[4];
            uint32_t base_off = (wrow + mt * 16 + arow) * ROWB_GATE + ks * 32 + abyt;
            LDSM_X4(ah[0], ah[1], ah[2], ah[3], sGhb + base_off);
            LDSM_X4(al[0], al[1], al[2], al[3], sGlb + base_off);
            #pragma unroll
            for (int nt = 0; nt < 2; nt++) {
                mma_fp16(c[nt][0], c[nt][1], c[nt][2], c[nt][3],
                         ah[0], ah[1], ah[2], ah[3], bh[ks][nt][0], bh[ks][nt][1]);
                mma_fp16(c[nt][0], c[nt][1], c[nt][2], c[nt][3],
                         ah[0], ah[1], ah[2], ah[3], bl[ks][nt][0], bl[ks][nt][1]);
                mma_fp16(c[nt][0], c[nt][1], c[nt][2], c[nt][3],
                         al[0], al[1], al[2], al[3], bh[ks][nt][0], bh[ks][nt][1]);
            }
        }

        #pragma unroll
        for (int nt = 0; nt < 2; nt++) {
            int h0 = nt * 8 + t4 * 2;
            float bb0 = bg[h0], bb1 = bg[h0 + 1];
            #pragma unroll
            for (int p = 0; p < 2; p++) {
                int row = rowbase + wrow + mt * 16 + g + p * 8;   // = r'
                int bidx = row / 10000;
                int rem  = row - bidx * 10000;                    // = j*100+i
                __half* dst = g_GW + (size_t)bidx * 160000 + rem;
                float v0 = fmaxf(c[nt][p * 2 + 0] + bb0, 1e-6f) * GW_SCALE;
                float v1 = fmaxf(c[nt][p * 2 + 1] + bb1, 1e-6f) * GW_SCALE;
                dst[(size_t)h0 * 10000]       = __float2half_rn(v0);
                dst[(size_t)(h0 + 1) * 10000] = __float2half_rn(v1);
            }
        }
    }
}

// ---------------------------------------------------------------------------
// Attention per (b,h). 512 threads (16 warps, 4x4 grid), 2 CTAs/SM.
// V read from g_Ah (fp16). SMEM total 110096 bytes (layout per R10).
// ---------------------------------------------------------------------------
#define ATTN_SMEM_BYTES 110096

__global__ __launch_bounds__(512, 2)
void attn_kernel(const float* __restrict__ wsp, const float* __restrict__ bsp,
                 float* __restrict__ out)
{
    extern __shared__ __align__(16) char smc[];
    __half* sKh  = (__half*)(smc);
    __half* sQh  = (__half*)(smc + 18432);
    __half* sPT  = (__half*)(smc);                 // overlays K/Q after phase 1
    float*  sS   = (float*) (smc + 36864);
    __half* sVT  = (__half*)(smc + 78864);
    float*  sInv = (float*) (smc + 109584);

    const int h = blockIdx.x, b = blockIdx.y;
    const int tid = threadIdx.x;
    const int wid = tid >> 5, lane = tid & 31;
    const int wm = wid & 3, wn = wid >> 2;            // 4 x 4 warp grid
    const int g = lane >> 2, t4 = lane & 3;

    // ---- initial loads: K, Q (+pad) AND V (overlaps phase-1 compute) ----
    const __half* Kg = g_Kh + (size_t)(b * 100) * 1024 + h * 64;
    const __half* Qg = g_Qh + (size_t)(b * 100) * 1024 + h * 64;
    for (int v = tid; v < 800; v += 512) {            // 100 rows x 8 x 16B
        int r = v >> 3, c = v & 7;
        *(uint4*)(sKh + r * 72 + c * 8) = *(const uint4*)(Kg + (size_t)r * 1024 + c * 8);
        *(uint4*)(sQh + r * 72 + c * 8) = *(const uint4*)(Qg + (size_t)r * 1024 + c * 8);
    }
    for (int v = tid; v < 224; v += 512) {            // zero K/Q pad rows 100..127
        int r = 100 + (v >> 3), c = v & 7;
        *(uint4*)(sKh + r * 72 + c * 8) = make_uint4(0, 0, 0, 0);
        *(uint4*)(sQh + r * 72 + c * 8) = make_uint4(0, 0, 0, 0);
    }
    // V from g_Ah (fp16): 100 rows x 16 chunks of 8 halves (16B)
    const __half* Vg = g_Ah + (size_t)(b * 100) * 2048 + h * 128;
    for (int v = tid; v < 1600; v += 512) {
        int i = v >> 4, c = v & 15;
        *(uint4*)(sVT + i * 136 + c * 8) = *(const uint4*)(Vg + (size_t)i * 2048 + c * 8);
    }
    for (int v = tid; v < 204; v += 512)              // zero sVT rows i=100..111
        ((uint4*)((char*)sVT + 27200))[v] = make_uint4(0, 0, 0, 0);
    __syncthreads();

    const int arow = lane & 15, abyt = (lane >> 4) << 4;
    const int brow = (lane & 7) + ((lane >> 4) << 3), bbyt = ((lane >> 3) & 1) << 4;

    // ---- Phase 1: S = K.Q^T * 0.125 (warp tile 32m x 32n) ----
    {
        float c1[2][4][4];
        #pragma unroll
        for (int i = 0; i < 2; i++)
            #pragma unroll
            for (int j = 0; j < 4; j++)
                #pragma unroll
                for (int k = 0; k < 4; k++) c1[i][j][k] = 0.f;
        const uint32_t sKb = smem_u32(sKh), sQb = smem_u32(sQh);
        #pragma unroll
        for (int ks = 0; ks < 4; ks++) {
            uint32_t af[2][4], bfr[2][4];
            #pragma unroll
            for (int fm = 0; fm < 2; fm++) {
                uint32_t ad = sKb + (wm * 32 + fm * 16 + arow) * 144 + ks * 32 + abyt;
                LDSM_X4(af[fm][0], af[fm][1], af[fm][2], af[fm][3], ad);
            }
            #pragma unroll
            for (int f2 = 0; f2 < 2; f2++) {
                uint32_t bd = sQb + (wn * 32 + f2 * 16 + brow) * 144 + ks * 32 + bbyt;
                LDSM_X4(bfr[f2][0], bfr[f2][1], bfr[f2][2], bfr[f2][3], bd);
            }
            #pragma unroll
            for (int fm = 0; fm < 2; fm++)
                #pragma unroll
                for (int fn = 0; fn < 4; fn++)
                    mma_fp16(c1[fm][fn][0], c1[fm][fn][1], c1[fm][fn][2], c1[fm][fn][3],
                             af[fm][0], af[fm][1], af[fm][2], af[fm][3],
                             bfr[fn >> 1][(fn & 1) * 2], bfr[fn >> 1][(fn & 1) * 2 + 1]);
        }
        #pragma unroll
        for (int fm = 0; fm < 2; fm++) {
            int i0 = wm * 32 + fm * 16 + g;
            #pragma unroll
            for (int fn = 0; fn < 4; fn++) {
                int j0 = wn * 32 + fn * 8 + t4 * 2;
                if (j0 < 100) {
                    if (i0 < 100) {
                        sS[i0 * 105 + j0]     = c1[fm][fn][0] * 0.125f;
                        sS[i0 * 105 + j0 + 1] = c1[fm][fn][1] * 0.125f;
                    }
                    if (i0 + 8 < 100) {
                        sS[(i0 + 8) * 105 + j0]     = c1[fm][fn][2] * 0.125f;
                        sS[(i0 + 8) * 105 + j0 + 1] = c1[fm][fn][3] * 0.125f;
                    }
                }
            }
        }
    }
    __syncthreads();   // K/Q dead from here; region0 becomes sPT

    // ---- zero sPT pad rows j=100..127 (240B each) ----
    for (int v = tid; v < 420; v += 512)
        ((uint4*)((char*)sPT + 24000))[v] = make_uint4(0, 0, 0, 0);

    // ---- softmax (warp per column j), unrolled 4 i-slots ----
    const __half* GWT = g_GW + (size_t)(b * 16 + h) * 10000;   // [j][i]
    for (int j = wid; j < 100; j += 16) {
        float g0 = __half2float(GWT[j * 100 + lane]);
        float g1 = __half2float(GWT[j * 100 + lane + 32]);
        float g2 = __half2float(GWT[j * 100 + lane + 64]);
        float g3 = (lane < 4) ? __half2float(GWT[j * 100 + lane + 96]) : 0.f;

        float s0 = sS[lane * 105 + j];
        float s1 = sS[(lane + 32) * 105 + j];
        float s2 = sS[(lane + 64) * 105 + j];
        float s3 = (lane < 4) ? sS[(lane + 96) * 105 + j] : -1e30f;

        float m = fmaxf(fmaxf(s0, s1), fmaxf(s2, s3));
        #pragma unroll
        for (int o = 16; o; o >>= 1) m = fmaxf(m, __shfl_xor_sync(~0u, m, o));

        float e0 = g0 * __expf(s0 - m);
        float e1 = g1 * __expf(s1 - m);
        float e2 = g2 * __expf(s2 - m);
        float e3 = (lane < 4) ? g3 * __expf(s3 - m) : 0.f;

        float s  = e0 + e1 + e2 + e3;
        float mx = fmaxf(fmaxf(e0, e1), fmaxf(e2, e3));
        #pragma unroll
        for (int o = 16; o; o >>= 1) {
            s  += __shfl_xor_sync(~0u, s, o);
            mx  = fmaxf(mx, __shfl_xor_sync(~0u, mx, o));
        }
        const float inv_mx = 1.f / mx;
        sPT[j * 120 + lane]      = __float2half_rn(e0 * inv_mx);
        sPT[j * 120 + lane + 32] = __float2half_rn(e1 * inv_mx);
        sPT[j * 120 + lane + 64] = __float2half_rn(e2 * inv_mx);
        if (lane < 4)  sPT[j * 120 + lane + 96]  = __float2half_rn(e3 * inv_mx);
        if (lane < 12) sPT[j * 120 + 100 + lane] = __float2half_rn(0.f);
        if (lane == 0) sInv[j] = mx / s;              // exact renormalization
    }
    __syncthreads();

    // ---- Phase 2: out = P^T · V  (m=j, k=i 112, n=d 128; warp 32j x 32d) ----
    {
        float c2[2][4][4];
        #pragma unroll
        for (int i = 0; i < 2; i++)
            #pragma unroll
            for (int j = 0; j < 4; j++)
                #pragma unroll
                for (int k = 0; k < 4; k++) c2[i][j][k] = 0.f;
        const uint32_t sPb = smem_u32(sPT), sVb = smem_u32(sVT);
        #pragma unroll
        for (int ks = 0; ks < 7; ks++) {
            uint32_t af[2][4], bfr[2][4];
            #pragma unroll
            for (int fm = 0; fm < 2; fm++) {
                uint32_t ad = sPb + (wm * 32 + fm * 16 + arow) * 240 + ks * 32 + abyt;
                LDSM_X4(af[fm][0], af[fm][1], af[fm][2], af[fm][3], ad);
            }
            #pragma unroll
            for (int f2 = 0; f2 < 2; f2++) {
                uint32_t bd = sVb + (ks * 16 + (lane & 15)) * 272
                            + (wn * 32 + f2 * 16) * 2 + ((lane >> 4) << 4);
                LDSM_X4_TRANS(bfr[f2][0], bfr[f2][1], bfr[f2][2], bfr[f2][3], bd);
            }
            #pragma unroll
            for (int fm = 0; fm < 2; fm++)
                #pragma unroll
                for (int fn = 0; fn < 4; fn++)
                    mma_fp16(c2[fm][fn][0], c2[fm][fn][1], c2[fm][fn][2], c2[fm][fn][3],
                             af[fm][0], af[fm][1], af[fm][2], af[fm][3],
                             bfr[fn >> 1][(fn & 1) * 2], bfr[fn >> 1][(fn & 1) * 2 + 1]);
        }
        const float wsc = *wsp, bsc = *bsp;
        #pragma unroll
        for (int fm = 0; fm < 2; fm++) {
            int j0 = wm * 32 + fm * 16 + g;
            #pragma unroll
            for (int fn = 0; fn < 4; fn++) {
                int d0 = wn * 32 + fn * 8 + t4 * 2;
                if (j0 < 100) {
                    float sc = sInv[j0] * wsc;
                    *(float2*)(out + (size_t)(b * 100 + j0) * 2048 + h * 128 + d0) =
                        make_float2(c2[fm][fn][0] * sc + bsc, c2[fm][fn][1] * sc + bsc);
                }
                if (j0 + 8 < 100) {
                    float sc = sInv[j0 + 8] * wsc;
                    *(float2*)(out + (size_t)(b * 100 + j0 + 8) * 2048 + h * 128 + d0) =
                        make_float2(c2[fm][fn][2] * sc + bsc, c2[fm][fn][3] * sc + bsc);
                }
            }
        }
    }
}

// ---------------------------------------------------------------------------
// Launch. DAG: prep -> { gemm(main) || gate(low-prio) } -> attn.
// Fork point is AFTER prep so gate is pending exactly when gemm's tail wave
// frees ~88 SMs (2 gemm CTAs/SM hold ALL regs+smem during full waves; tail
// slots have room for gate's 10K regs + 74KB smem). Gate's DRAM traffic hides
// under tensor-bound gemm instead of contending with DRAM-bound prep.
// Inputs: a_features, g_features, split, rel_pair_counts,
// W_g, b_g, W_K, b_K, W_Q, b_Q, w_s, b_s
// ---------------------------------------------------------------------------
extern "C" void kernel_launch(void* const* d_in, const int* in_sizes, int n_in,
                              void* d_out, int out_size)
{
    (void)in_sizes; (void)n_in; (void)out_size;
    const float* a  = (const float*)d_in[0];
    const float* gf = (const float*)d_in[1];
    const float* Wg = (const float*)d_in[4];
    const float* bg = (const float*)d_in[5];
    const float* Wk = (const float*)d_in[6];
    const float* bk = (const float*)d_in[7];
    const float* Wq = (const float*)d_in[8];
    const float* bq = (const float*)d_in[9];
    const float* ws = (const float*)d_in[10];
    const float* bs = (const float*)d_in[11];
    float* out = (float*)d_out;

    cudaFuncSetAttribute(gemm_kernel, cudaFuncAttributeMaxDynamicSharedMemorySize, GEMM_SMEM);
    cudaFuncSetAttribute(attn_kernel, cudaFuncAttributeMaxDynamicSharedMemorySize,
                         ATTN_SMEM_BYTES);

    int prLow = 0, prHigh = 0;
    cudaDeviceGetStreamPriorityRange(&prLow, &prHigh);   // prLow = numerically lowest priority

    cudaStream_t s2;
    cudaStreamCreateWithPriority(&s2, cudaStreamNonBlocking, prLow);
    cudaEvent_t evFork, evJoin;
    cudaEventCreateWithFlags(&evFork, cudaEventDisableTiming);
    cudaEventCreateWithFlags(&evJoin, cudaEventDisableTiming);

    // critical path first
    prep_kernel<<<PREP_BLOCKS, 256>>>(a, Wk, Wq);

    // fork AFTER prep: gate runs concurrent with gemm (fills gemm's tail wave)
    cudaEventRecord(evFork, 0);
    cudaStreamWaitEvent(s2, evFork, 0);
    gate_kernel<<<640000 / GATE_ROWS, 256, 0, s2>>>(gf, Wg, bg);

    gemm_kernel<<<dim3(16, 50), 256, GEMM_SMEM>>>(bk, bq);

    // join: attn needs gate's output (and gemm's, via stream order)
    cudaEventRecord(evJoin, s2);
    cudaStreamWaitEvent(0, evJoin, 0);

    attn_kernel<<<dim3(16, 64), 512, ATTN_SMEM_BYTES>>>(ws, bs, out);

    cudaStreamDestroy(s2);
    cudaEventDestroy(evFork);
    cudaEventDestroy(evJoin);
}

// round 16
// speedup vs baseline: 1.0440x; 1.0440x over previous
#include <cuda_runtime.h>
#include <cuda_fp16.h>
#include <cstdint>

// Problem constants
#define BB   64
#define NN   100
#define DD   2048
#define NRH  16
#define PP   (BB*NN)        // 6400

#define GW_SCALE 1024.0f    // uniform gate scale; cancels exactly in softmax ratio

// ---------------------------------------------------------------------------
// Scratch (__device__ globals; no allocations allowed)
// ---------------------------------------------------------------------------
__device__ __half g_Ah[PP * 2048];               // 26.2 MB  A in fp16 (also V source)
__device__ __half g_Wh[2048 * 2048];             // 8.4 MB   W^T fused [n][k] (Wk|Wq)
__device__ __half g_Kh[PP * 1024];               // 13.1 MB  K fp16
__device__ __half g_Qh[PP * 1024];               // 13.1 MB  Q fp16
__device__ __half g_GW[BB * NRH * NN * NN];      // 20.5 MB  gw*1024 fp16, [b][h][j][i]

__device__ __forceinline__ uint32_t smem_u32(const void* p) {
    uint32_t a;
    asm("{ .reg .u64 t; cvta.to.shared.u64 t, %1; cvt.u32.u64 %0, t; }" : "=r"(a) : "l"(p));
    return a;
}

#define CP_ASYNC16(dst, src) \
    asm volatile("cp.async.cg.shared.global [%0], [%1], 16;" :: "r"(dst), "l"(src) : "memory")
#define CP_COMMIT() asm volatile("cp.async.commit_group;" ::: "memory")
#define CP_WAIT1()  asm volatile("cp.async.wait_group 1;" ::: "memory")
#define CP_WAIT0()  asm volatile("cp.async.wait_group 0;" ::: "memory")

// Non-volatile: barriers fence smem ordering; lets ptxas interleave with mma.
#define LDSM_X4(r0, r1, r2, r3, addr) \
    asm("ldmatrix.sync.aligned.m8n8.x4.shared.b16 {%0,%1,%2,%3}, [%4];" \
        : "=r"(r0), "=r"(r1), "=r"(r2), "=r"(r3) : "r"(addr))

#define LDSM_X4_TRANS(r0, r1, r2, r3, addr) \
    asm("ldmatrix.sync.aligned.m8n8.x4.trans.shared.b16 {%0,%1,%2,%3}, [%4];" \
        : "=r"(r0), "=r"(r1), "=r"(r2), "=r"(r3) : "r"(addr))

__device__ __forceinline__ void mma_fp16(float& c0, float& c1, float& c2, float& c3,
                                         uint32_t a0, uint32_t a1, uint32_t a2, uint32_t a3,
                                         uint32_t b0, uint32_t b1)
{
    asm("mma.sync.aligned.m16n8k16.row.col.f32.f16.f16.f32 "
        "{%0,%1,%2,%3}, {%4,%5,%6,%7}, {%8,%9}, {%0,%1,%2,%3};"
        : "+f"(c0), "+f"(c1), "+f"(c2), "+f"(c3)
        : "r"(a0), "r"(a1), "r"(a2), "r"(a3), "r"(b0), "r"(b1));
}

// ---------------------------------------------------------------------------
// Fused prep: blocks [0, 12800) = A fp32->fp16; [12800, 16896) = W transpose.
// ---------------------------------------------------------------------------
#define PREP_A_BLOCKS 12800
#define PREP_BLOCKS   (PREP_A_BLOCKS + 4096)

__global__ __launch_bounds__(256)
void prep_kernel(const float* __restrict__ A,
                 const float* __restrict__ Wk, const float* __restrict__ Wq)
{
    __shared__ float t[32][33];
    if (blockIdx.x < PREP_A_BLOCKS) {
        int id = blockIdx.x * 256 + threadIdx.x;   // one float4 each
        float4 v = *(const float4*)(A + (size_t)id * 4);
        __half h[4] = {__float2half_rn(v.x), __float2half_rn(v.y),
                       __float2half_rn(v.z), __float2half_rn(v.w)};
        *(uint2*)(g_Ah + (size_t)id * 4) = *(uint2*)h;
    } else {
        int bid = blockIdx.x - PREP_A_BLOCKS;      // 4096 = 64 x 64
        const int k0 = (bid & 63) * 32, n0 = (bid >> 6) * 32;
        const float* src = (n0 < 1024) ? Wk : Wq;
        const int nc0 = (n0 < 1024) ? n0 : n0 - 1024;
        const int tx = threadIdx.x & 31, ty = threadIdx.x >> 5;
        for (int r = ty; r < 32; r += 8)
            t[r][tx] = src[(k0 + r) * 1024 + nc0 + tx];
        __syncthreads();
        for (int r = ty; r < 32; r += 8)
            g_Wh[(size_t)(n0 + r) * 2048 + k0 + tx] = __float2half_rn(t[tx][r]);
    }
}

// ---------------------------------------------------------------------------
// fp16 GEMM: C[6400 x 2048] = Ah @ Wh^T (+bias)  ->  g_Kh | g_Qh (fp16)
// Tiles BM=128 BN=128 BK=64; 3-stage cp.async; 8 warps (2m x 4n), warp 64x32.
// ---------------------------------------------------------------------------
#define ROWH 72
#define ROWB 144
#define TILE_BYTES2 (128 * ROWB)                   // 18432 per operand
#define STAGE_BYTES2 (2 * TILE_BYTES2)             // 36864
#define NSTAGE 3
#define NITER  32                                  // 2048 / 64
#define GEMM_SMEM (NSTAGE * STAGE_BYTES2)          // 110592 B

__global__ __launch_bounds__(256, 2)
void gemm_kernel(const float* __restrict__ bk, const float* __restrict__ bq)
{
    extern __shared__ __align__(16) __half sm[];

    const int tid  = threadIdx.x;
    const int wid  = tid >> 5, lane = tid & 31;
    const int wm   = wid & 1,  wn   = wid >> 1;       // 2 x 4 warp grid
    const int g    = lane >> 2, t4  = lane & 3;
    const int mbase = blockIdx.y * 128;
    const int nbase = blockIdx.x * 128;

    const uint32_t sbase = smem_u32(sm);
    const __half* gA = g_Ah + (size_t)mbase * 2048;
    const __half* gB = g_Wh + (size_t)nbase * 2048;

    auto load_stage = [&](int it, int s) {
        const int k0 = it * 64;
        const uint32_t sA = sbase + s * STAGE_BYTES2;
        const uint32_t sB = sA + TILE_BYTES2;
        #pragma unroll
        for (int l = 0; l < 4; l++) {
            int q = tid + 256 * l;
            int r = q >> 3, c = q & 7;
            CP_ASYNC16(sA + r * ROWB + c * 16,
                       (const char*)(gA + (size_t)r * 2048 + k0 + c * 8));
            CP_ASYNC16(sB + r * ROWB + c * 16,
                       (const char*)(gB + (size_t)r * 2048 + k0 + c * 8));
        }
        CP_COMMIT();
    };

    float c[4][4][4];
    #pragma unroll
    for (int i = 0; i < 4; i++)
        #pragma unroll
        for (int j = 0; j < 4; j++)
            #pragma unroll
            for (int k = 0; k < 4; k++) c[i][j][k] = 0.f;

    load_stage(0, 0);
    load_stage(1, 1);

    const int arow = (lane & 15);
    const int abyt = (lane >> 4) << 4;
    const int brow = (lane & 7) + ((lane >> 4) << 3);
    const int bbyt = ((lane >> 3) & 1) << 4;

    for (int it = 0; it < NITER; ++it) {
        const int s = it % NSTAGE;
        if (it < NITER - 1) { CP_WAIT1(); } else { CP_WAIT0(); }
        __syncthreads();
        if (it + 2 < NITER) load_stage(it + 2, (it + 2) % NSTAGE);

        const uint32_t sA = sbase + s * STAGE_BYTES2;
        const uint32_t sB = sA + TILE_BYTES2;

        #pragma unroll
        for (int ks = 0; ks < 4; ks++) {
            uint32_t af[4][4], bfr[2][4];
            #pragma unroll
            for (int fm = 0; fm < 4; fm++) {
                uint32_t ad = sA + (wm * 64 + fm * 16 + arow) * ROWB + ks * 32 + abyt;
                LDSM_X4(af[fm][0], af[fm][1], af[fm][2], af[fm][3], ad);
            }
            #pragma unroll
            for (int f2 = 0; f2 < 2; f2++) {
                uint32_t bd = sB + (wn * 32 + f2 * 16 + brow) * ROWB + ks * 32 + bbyt;
                LDSM_X4(bfr[f2][0], bfr[f2][1], bfr[f2][2], bfr[f2][3], bd);
            }
            #pragma unroll
            for (int fm = 0; fm < 4; fm++)
                #pragma unroll
                for (int fn = 0; fn < 4; fn++) {
                    uint32_t b0 = bfr[fn >> 1][(fn & 1) * 2 + 0];
                    uint32_t b1 = bfr[fn >> 1][(fn & 1) * 2 + 1];
                    mma_fp16(c[fm][fn][0], c[fm][fn][1], c[fm][fn][2], c[fm][fn][3],
                             af[fm][0], af[fm][1], af[fm][2], af[fm][3], b0, b1);
                }
        }
    }

    const bool side = (nbase >= 1024);
    const float* bsrc = side ? bq : bk;
    __half* outh = side ? g_Qh : g_Kh;
    const int colb = side ? (nbase - 1024) : nbase;

    #pragma unroll
    for (int fm = 0; fm < 4; fm++) {
        int row = mbase + wm * 64 + fm * 16 + g;
        #pragma unroll
        for (int fn = 0; fn < 4; fn++) {
            int col = colb + wn * 32 + fn * 8 + t4 * 2;
            float b0 = bsrc[col], b1 = bsrc[col + 1];
            *(__half2*)(outh + (size_t)row * 1024 + col) =
                __floats2half2_rn(c[fm][fn][0] + b0, c[fm][fn][1] + b1);
            *(__half2*)(outh + (size_t)(row + 8) * 1024 + col) =
                __floats2half2_rn(c[fm][fn][2] + b0, c[fm][fn][3] + b1);
        }
    }
}

// ---------------------------------------------------------------------------
// Gate via fp16 mma, hi/lo split. Rows in (b, j, i)-PERMUTED order so the
// output scatter g_GW[b][h][j][i] keeps contiguous 16B runs per 8 lanes.
// ---------------------------------------------------------------------------
#define GATE_ROWS 256
#define GATE_RH   72
#define ROWB_GATE 144

__global__ __launch_bounds__(256, 2)
void gate_kernel(const float* __restrict__ gf,
                 const float* __restrict__ Wg, const float* __restrict__ bg)
{
    __shared__ __align__(16) __half sGh[GATE_ROWS * GATE_RH];
    __shared__ __align__(16) __half sGl[GATE_ROWS * GATE_RH];

    const int tid = threadIdx.x, lane = tid & 31, wid = tid >> 5;
    const int g = lane >> 2, t4 = lane & 3;
    const int rowbase = blockIdx.x * GATE_ROWS;

    {
        const int r0 = tid >> 4;
        const int c4 = (tid & 15) << 2;
        #pragma unroll
        for (int l = 0; l < 16; l++) {
            int r  = r0 + l * 16;
            int rp = rowbase + r;
            int bb = rp / 10000;
            int remp = rp - bb * 10000;            // = j*100 + i
            int jj = remp / 100;
            int ii = remp - jj * 100;
            float4 x = *(const float4*)(gf + ((size_t)bb * 10000 + ii * 100 + jj) * 64 + c4);
            float xs[4] = {x.x, x.y, x.z, x.w};
            __half hi[4], lo[4];
            #pragma unroll
            for (int e = 0; e < 4; e++) {
                hi[e] = __float2half_rn(xs[e]);
                lo[e] = __float2half_rn(xs[e] - __half2float(hi[e]));
            }
            *(uint2*)(sGh + r * GATE_RH + c4) = *(uint2*)hi;
            *(uint2*)(sGl + r * GATE_RH + c4) = *(uint2*)lo;
        }
    }

    uint32_t bh[4][2][2], bl[4][2][2];
    #pragma unroll
    for (int ks = 0; ks < 4; ks++)
        #pragma unroll
        for (int nt = 0; nt < 2; nt++) {
            int n = nt * 8 + g;
            #pragma unroll
            for (int rg = 0; rg < 2; rg++) {
                int k0 = ks * 16 + t4 * 2 + rg * 8;
                float w0 = Wg[k0 * 16 + n], w1 = Wg[(k0 + 1) * 16 + n];
                __half h0 = __float2half_rn(w0), h1 = __float2half_rn(w1);
                __half l0 = __float2half_rn(w0 - __half2float(h0));
                __half l1 = __float2half_rn(w1 - __half2float(h1));
                __half hh[2] = {h0, h1}, ll[2] = {l0, l1};
                bh[ks][nt][rg] = *(uint32_t*)hh;
                bl[ks][nt][rg] = *(uint32_t*)ll;
            }
        }
    __syncthreads();

    const uint32_t sGhb = smem_u32(sGh), sGlb = smem_u32(sGl);
    const int arow = lane & 15, abyt = (lane >> 4) << 4;
    const int wrow = wid * 32;

    #pragma unroll
    for (int mt = 0; mt < 2; mt++) {
        float c[2][4];
        #pragma unroll
        for (int nt = 0; nt < 2; nt++)
            #pragma unroll
            for (int k = 0; k < 4; k++) c[nt][k] = 0.f;

        #pragma unroll
        for (int ks = 0; ks < 4; ks++) {
            uint32_t ah[4], al[4];
            uint32_t base_off = (wrow + mt * 16 + arow) * ROWB_GATE + ks * 32 + abyt;
            LDSM_X4(ah[0], ah[1], ah[2], ah[3], sGhb + base_off);
            LDSM_X4(al[0], al[1], al[2], al[3], sGlb + base_off);
            #pragma unroll
            for (int nt = 0; nt < 2; nt++) {
                mma_fp16(c[nt][0], c[nt][1], c[nt][2], c[nt][3],
                         ah[0], ah[1], ah[2], ah[3], bh[ks][nt][0], bh[ks][nt][1]);
                mma_fp16(c[nt][0], c[nt][1], c[nt][2], c[nt][3],
                         ah[0], ah[1], ah[2], ah[3], bl[ks][nt][0], bl[ks][nt][1]);
                mma_fp16(c[nt][0], c[nt][1], c[nt][2], c[nt][3],
                         al[0], al[1], al[2], al[3], bh[ks][nt][0], bh[ks][nt][1]);
            }
        }

        #pragma unroll
        for (int nt = 0; nt < 2; nt++) {
            int h0 = nt * 8 + t4 * 2;
            float bb0 = bg[h0], bb1 = bg[h0 + 1];
            #pragma unroll
            for (int p = 0; p < 2; p++) {
                int row = rowbase + wrow + mt * 16 + g + p * 8;   // = r'
                int bidx = row / 10000;
                int rem  = row - bidx * 10000;                    // = j*100+i
                __half* dst = g_GW + (size_t)bidx * 160000 + rem;
                float v0 = fmaxf(c[nt][p * 2 + 0] + bb0, 1e-6f) * GW_SCALE;
                float v1 = fmaxf(c[nt][p * 2 + 1] + bb1, 1e-6f) * GW_SCALE;
                dst[(size_t)h0 * 10000]       = __float2half_rn(v0);
                dst[(size_t)(h0 + 1) * 10000] = __float2half_rn(v1);
            }
        }
    }
}

// ---------------------------------------------------------------------------
// Attention per (b,h). 512 threads (16 warps, 4x4 grid), 2 CTAs/SM.
// K/Q/V staged via cp.async (no register staging); softmax gw loads software-
// pipelined (prefetch column j+16 while reducing column j).
// SMEM total 110096 bytes (layout per R10).
// ---------------------------------------------------------------------------
#define ATTN_SMEM_BYTES 110096

__global__ __launch_bounds__(512, 2)
void attn_kernel(const float* __restrict__ wsp, const float* __restrict__ bsp,
                 float* __restrict__ out)
{
    extern __shared__ __align__(16) char smc[];
    __half* sKh  = (__half*)(smc);
    __half* sQh  = (__half*)(smc + 18432);
    __half* sPT  = (__half*)(smc);                 // overlays K/Q after phase 1
    float*  sS   = (float*) (smc + 36864);
    __half* sVT  = (__half*)(smc + 78864);
    float*  sInv = (float*) (smc + 109584);

    const int h = blockIdx.x, b = blockIdx.y;
    const int tid = threadIdx.x;
    const int wid = tid >> 5, lane = tid & 31;
    const int wm = wid & 3, wn = wid >> 2;            // 4 x 4 warp grid
    const int g = lane >> 2, t4 = lane & 3;

    // ---- initial loads via cp.async: K, Q, V (all 16B-aligned chunks) ----
    const __half* Kg = g_Kh + (size_t)(b * 100) * 1024 + h * 64;
    const __half* Qg = g_Qh + (size_t)(b * 100) * 1024 + h * 64;
    const __half* Vg = g_Ah + (size_t)(b * 100) * 2048 + h * 128;
    const uint32_t sKb0 = smem_u32(sKh), sQb0 = smem_u32(sQh), sVb0 = smem_u32(sVT);

    for (int v = tid; v < 800; v += 512) {            // K,Q: 100 rows x 8 x 16B
        int r = v >> 3, c = v & 7;
        CP_ASYNC16(sKb0 + r * 144 + c * 16, (const char*)(Kg + (size_t)r * 1024 + c * 8));
        CP_ASYNC16(sQb0 + r * 144 + c * 16, (const char*)(Qg + (size_t)r * 1024 + c * 8));
    }
    for (int v = tid; v < 1600; v += 512) {           // V: 100 rows x 16 x 16B
        int i = v >> 4, c = v & 15;
        CP_ASYNC16(sVb0 + i * 272 + c * 16, (const char*)(Vg + (size_t)i * 2048 + c * 8));
    }
    CP_COMMIT();

    for (int v = tid; v < 224; v += 512) {            // zero K/Q pad rows 100..127
        int r = 100 + (v >> 3), c = v & 7;
        *(uint4*)(sKh + r * 72 + c * 8) = make_uint4(0, 0, 0, 0);
        *(uint4*)(sQh + r * 72 + c * 8) = make_uint4(0, 0, 0, 0);
    }
    for (int v = tid; v < 204; v += 512)              // zero sVT rows i=100..111
        ((uint4*)((char*)sVT + 27200))[v] = make_uint4(0, 0, 0, 0);

    CP_WAIT0();
    __syncthreads();

    const int arow = lane & 15, abyt = (lane >> 4) << 4;
    const int brow = (lane & 7) + ((lane >> 4) << 3), bbyt = ((lane >> 3) & 1) << 4;

    // ---- Phase 1: S = K.Q^T * 0.125 (warp tile 32m x 32n) ----
    {
        float c1[2][4][4];
        #pragma unroll
        for (int i = 0; i < 2; i++)
            #pragma unroll
            for (int j = 0; j < 4; j++)
                #pragma unroll
                for (int k = 0; k < 4; k++) c1[i][j][k] = 0.f;
        #pragma unroll
        for (int ks = 0; ks < 4; ks++) {
            uint32_t af[2][4], bfr[2][4];
            #pragma unroll
            for (int fm = 0; fm < 2; fm++) {
                uint32_t ad = sKb0 + (wm * 32 + fm * 16 + arow) * 144 + ks * 32 + abyt;
                LDSM_X4(af[fm][0], af[fm][1], af[fm][2], af[fm][3], ad);
            }
            #pragma unroll
            for (int f2 = 0; f2 < 2; f2++) {
                uint32_t bd = sQb0 + (wn * 32 + f2 * 16 + brow) * 144 + ks * 32 + bbyt;
                LDSM_X4(bfr[f2][0], bfr[f2][1], bfr[f2][2], bfr[f2][3], bd);
            }
            #pragma unroll
            for (int fm = 0; fm < 2; fm++)
                #pragma unroll
                for (int fn = 0; fn < 4; fn++)
                    mma_fp16(c1[fm][fn][0], c1[fm][fn][1], c1[fm][fn][2], c1[fm][fn][3],
                             af[fm][0], af[fm][1], af[fm][2], af[fm][3],
                             bfr[fn >> 1][(fn & 1) * 2], bfr[fn >> 1][(fn & 1) * 2 + 1]);
        }
        #pragma unroll
        for (int fm = 0; fm < 2; fm++) {
            int i0 = wm * 32 + fm * 16 + g;
            #pragma unroll
            for (int fn = 0; fn < 4; fn++) {
                int j0 = wn * 32 + fn * 8 + t4 * 2;
                if (j0 < 100) {
                    if (i0 < 100) {
                        sS[i0 * 105 + j0]     = c1[fm][fn][0] * 0.125f;
                        sS[i0 * 105 + j0 + 1] = c1[fm][fn][1] * 0.125f;
                    }
                    if (i0 + 8 < 100) {
                        sS[(i0 + 8) * 105 + j0]     = c1[fm][fn][2] * 0.125f;
                        sS[(i0 + 8) * 105 + j0 + 1] = c1[fm][fn][3] * 0.125f;
                    }
                }
            }
        }
    }
    __syncthreads();   // K/Q dead from here; region0 becomes sPT

    // ---- zero sPT pad rows j=100..127 (240B each) ----
    for (int v = tid; v < 420; v += 512)
        ((uint4*)((char*)sPT + 24000))[v] = make_uint4(0, 0, 0, 0);

    // ---- softmax (warp per column j), gw prefetch pipelined ----
    const __half* GWT = g_GW + (size_t)(b * 16 + h) * 10000;   // [j][i]
    {
        int j = wid;
        float g0 = 0.f, g1 = 0.f, g2 = 0.f, g3 = 0.f;
        if (j < 100) {
            g0 = __half2float(GWT[j * 100 + lane]);
            g1 = __half2float(GWT[j * 100 + lane + 32]);
            g2 = __half2float(GWT[j * 100 + lane + 64]);
            g3 = (lane < 4) ? __half2float(GWT[j * 100 + lane + 96]) : 0.f;
        }
        #pragma unroll
        for (int jj = 0; jj < 7; jj++) {
            if (j >= 100) break;
            const int jn = j + 16;
            // prefetch next column's gw while we reduce this one
            float n0 = 0.f, n1 = 0.f, n2 = 0.f, n3 = 0.f;
            if (jn < 100) {
                n0 = __half2float(GWT[jn * 100 + lane]);
                n1 = __half2float(GWT[jn * 100 + lane + 32]);
                n2 = __half2float(GWT[jn * 100 + lane + 64]);
                n3 = (lane < 4) ? __half2float(GWT[jn * 100 + lane + 96]) : 0.f;
            }

            float s0 = sS[lane * 105 + j];
            float s1 = sS[(lane + 32) * 105 + j];
            float s2 = sS[(lane + 64) * 105 + j];
            float s3 = (lane < 4) ? sS[(lane + 96) * 105 + j] : -1e30f;

            float m = fmaxf(fmaxf(s0, s1), fmaxf(s2, s3));
            #pragma unroll
            for (int o = 16; o; o >>= 1) m = fmaxf(m, __shfl_xor_sync(~0u, m, o));

            float e0 = g0 * __expf(s0 - m);
            float e1 = g1 * __expf(s1 - m);
            float e2 = g2 * __expf(s2 - m);
            float e3 = (lane < 4) ? g3 * __expf(s3 - m) : 0.f;

            float s  = e0 + e1 + e2 + e3;
            float mx = fmaxf(fmaxf(e0, e1), fmaxf(e2, e3));
            #pragma unroll
            for (int o = 16; o; o >>= 1) {
                s  += __shfl_xor_sync(~0u, s, o);
                mx  = fmaxf(mx, __shfl_xor_sync(~0u, mx, o));
            }
            const float inv_mx = 1.f / mx;
            sPT[j * 120 + lane]      = __float2half_rn(e0 * inv_mx);
            sPT[j * 120 + lane + 32] = __float2half_rn(e1 * inv_mx);
            sPT[j * 120 + lane + 64] = __float2half_rn(e2 * inv_mx);
            if (lane < 4)  sPT[j * 120 + lane + 96]  = __float2half_rn(e3 * inv_mx);
            if (lane < 12) sPT[j * 120 + 100 + lane] = __float2half_rn(0.f);
            if (lane == 0) sInv[j] = mx / s;          // exact renormalization

            g0 = n0; g1 = n1; g2 = n2; g3 = n3;
            j = jn;
        }
    }
    __syncthreads();

    // ---- Phase 2: out = P^T · V  (m=j, k=i 112, n=d 128; warp 32j x 32d) ----
    {
        float c2[2][4][4];
        #pragma unroll
        for (int i = 0; i < 2; i++)
            #pragma unroll
            for (int j = 0; j < 4; j++)
                #pragma unroll
                for (int k = 0; k < 4; k++) c2[i][j][k] = 0.f;
        const uint32_t sPb = smem_u32(sPT);
        #pragma unroll
        for (int ks = 0; ks < 7; ks++) {
            uint32_t af[2][4], bfr[2][4];
            #pragma unroll
            for (int fm = 0; fm < 2; fm++) {
                uint32_t ad = sPb + (wm * 32 + fm * 16 + arow) * 240 + ks * 32 + abyt;
                LDSM_X4(af[fm][0], af[fm][1], af[fm][2], af[fm][3], ad);
            }
            #pragma unroll
            for (int f2 = 0; f2 < 2; f2++) {
                uint32_t bd = sVb0 + (ks * 16 + (lane & 15)) * 272
                            + (wn * 32 + f2 * 16) * 2 + ((lane >> 4) << 4);
                LDSM_X4_TRANS(bfr[f2][0], bfr[f2][1], bfr[f2][2], bfr[f2][3], bd);
            }
            #pragma unroll
            for (int fm = 0; fm < 2; fm++)
                #pragma unroll
                for (int fn = 0; fn < 4; fn++)
                    mma_fp16(c2[fm][fn][0], c2[fm][fn][1], c2[fm][fn][2], c2[fm][fn][3],
                             af[fm][0], af[fm][1], af[fm][2], af[fm][3],
                             bfr[fn >> 1][(fn & 1) * 2], bfr[fn >> 1][(fn & 1) * 2 + 1]);
        }
        const float wsc = *wsp, bsc = *bsp;
        #pragma unroll
        for (int fm = 0; fm < 2; fm++) {
            int j0 = wm * 32 + fm * 16 + g;
            #pragma unroll
            for (int fn = 0; fn < 4; fn++) {
                int d0 = wn * 32 + fn * 8 + t4 * 2;
                if (j0 < 100) {
                    float sc = sInv[j0] * wsc;
                    *(float2*)(out + (size_t)(b * 100 + j0) * 2048 + h * 128 + d0) =
                        make_float2(c2[fm][fn][0] * sc + bsc, c2[fm][fn][1] * sc + bsc);
                }
                if (j0 + 8 < 100) {
                    float sc = sInv[j0 + 8] * wsc;
                    *(float2*)(out + (size_t)(b * 100 + j0 + 8) * 2048 + h * 128 + d0) =
                        make_float2(c2[fm][fn][2] * sc + bsc, c2[fm][fn][3] * sc + bsc);
                }
            }
        }
    }
}

// ---------------------------------------------------------------------------
// Launch (R14 arrangement — best measured): gate forked at t=0 on a
// low-priority stream; prep -> gemm on main; join before attn.
// Inputs: a_features, g_features, split, rel_pair_counts,
// W_g, b_g, W_K, b_K, W_Q, b_Q, w_s, b_s
// ---------------------------------------------------------------------------
extern "C" void kernel_launch(void* const* d_in, const int* in_sizes, int n_in,
                              void* d_out, int out_size)
{
    (void)in_sizes; (void)n_in; (void)out_size;
    const float* a  = (const float*)d_in[0];
    const float* gf = (const float*)d_in[1];
    const float* Wg = (const float*)d_in[4];
    const float* bg = (const float*)d_in[5];
    const float* Wk = (const float*)d_in[6];
    const float* bk = (const float*)d_in[7];
    const float* Wq = (const float*)d_in[8];
    const float* bq = (const float*)d_in[9];
    const float* ws = (const float*)d_in[10];
    const float* bs = (const float*)d_in[11];
    float* out = (float*)d_out;

    cudaFuncSetAttribute(gemm_kernel, cudaFuncAttributeMaxDynamicSharedMemorySize, GEMM_SMEM);
    cudaFuncSetAttribute(attn_kernel, cudaFuncAttributeMaxDynamicSharedMemorySize,
                         ATTN_SMEM_BYTES);

    int prLow = 0, prHigh = 0;
    cudaDeviceGetStreamPriorityRange(&prLow, &prHigh);

    cudaStream_t s2;
    cudaStreamCreateWithPriority(&s2, cudaStreamNonBlocking, prLow);
    cudaEvent_t evFork, evJoin;
    cudaEventCreateWithFlags(&evFork, cudaEventDisableTiming);
    cudaEventCreateWithFlags(&evJoin, cudaEventDisableTiming);

    cudaEventRecord(evFork, 0);
    cudaStreamWaitEvent(s2, evFork, 0);

    gate_kernel<<<640000 / GATE_ROWS, 256, 0, s2>>>(gf, Wg, bg);    // low-prio branch

    prep_kernel<<<PREP_BLOCKS, 256>>>(a, Wk, Wq);                   // critical path
    gemm_kernel<<<dim3(16, 50), 256, GEMM_SMEM>>>(bk, bq);

    cudaEventRecord(evJoin, s2);
    cudaStreamWaitEvent(0, evJoin, 0);

    attn_kernel<<<dim3(16, 64), 512, ATTN_SMEM_BYTES>>>(ws, bs, out);

    cudaStreamDestroy(s2);
    cudaEventDestroy(evFork);
    cudaEventDestroy(evJoin);
}